// round 5
// baseline (speedup 1.0000x reference)
#include <cuda_runtime.h>
#include <cuda_bf16.h>

#define THREADS 256
// dynamic smem byte offsets
#define AHI_OFF 0
#define ALO_OFF 25600
#define WST_OFF 51200
#define Q_OFF   88064
#define K_OFF   125696
#define V_OFF   163328
#define LG_OFF  200960
#define LG_STRIDE 52
#define SMEM_BYTES 211152

__device__ __nv_bfloat16 g_Whi[110592];
__device__ __nv_bfloat16 g_Wlo[110592];
__device__ __nv_bfloat16 g_Phi[36864];
__device__ __nv_bfloat16 g_Plo[36864];

__global__ void prep_weights(const float* __restrict__ qkv_w,
                             const float* __restrict__ proj_w) {
    int i = blockIdx.x * 256 + threadIdx.x;
    if (i < 110592) {
        float v = qkv_w[i];
        __nv_bfloat16 h = __float2bfloat16(v);
        g_Whi[i] = h;
        g_Wlo[i] = __float2bfloat16(v - __bfloat162float(h));
    }
    if (i < 36864) {
        float v = proj_w[i];
        __nv_bfloat16 h = __float2bfloat16(v);
        g_Phi[i] = h;
        g_Plo[i] = __float2bfloat16(v - __bfloat162float(h));
    }
}

__device__ __forceinline__ unsigned long long pk2(float lo, float hi) {
    unsigned long long r;
    asm("mov.b64 %0, {%1, %2};" : "=l"(r) : "f"(lo), "f"(hi));
    return r;
}
__device__ __forceinline__ float2 unpk2(unsigned long long v) {
    float2 r;
    asm("mov.b64 {%0, %1}, %2;" : "=f"(r.x), "=f"(r.y) : "l"(v));
    return r;
}
__device__ __forceinline__ void fma2(unsigned long long& d, unsigned long long a,
                                     unsigned long long b) {
    asm("fma.rn.f32x2 %0, %1, %2, %0;" : "+l"(d) : "l"(a), "l"(b));
}
__device__ __forceinline__ unsigned pkbf(__nv_bfloat16 a, __nv_bfloat16 b) {
    return (unsigned)__bfloat16_as_ushort(a) | ((unsigned)__bfloat16_as_ushort(b) << 16);
}
__device__ __forceinline__ void mma_bf16(float* c, const unsigned* a, const unsigned* b) {
    asm volatile(
        "mma.sync.aligned.m16n8k16.row.col.f32.bf16.bf16.f32 "
        "{%0,%1,%2,%3}, {%4,%5,%6,%7}, {%8,%9}, {%0,%1,%2,%3};\n"
        : "+f"(c[0]), "+f"(c[1]), "+f"(c[2]), "+f"(c[3])
        : "r"(a[0]), "r"(a[1]), "r"(a[2]), "r"(a[3]), "r"(b[0]), "r"(b[1]));
}
__device__ __forceinline__ void ldsm4(unsigned* r, unsigned addr) {
    asm volatile("ldmatrix.sync.aligned.m8n8.x4.shared.b16 {%0,%1,%2,%3}, [%4];\n"
                 : "=r"(r[0]), "=r"(r[1]), "=r"(r[2]), "=r"(r[3]) : "r"(addr));
}

// C[49][192] = A(hi+lo)[64][192] @ W^T + bias, *scale.  W row-major [n][k] bf16 hi/lo.
__device__ __noinline__ void gemm_mma(const __nv_bfloat16* __restrict__ Whi,
                                      const __nv_bfloat16* __restrict__ Wlo,
                                      const float* __restrict__ bias,
                                      float scale, float* __restrict__ outp) {
    extern __shared__ char smem[];
    const __nv_bfloat16* Ah = (const __nv_bfloat16*)(smem + AHI_OFF);
    const __nv_bfloat16* Al = (const __nv_bfloat16*)(smem + ALO_OFF);
    char* wst = smem + WST_OFF;
    const unsigned wst_u32 = (unsigned)__cvta_generic_to_shared(wst);

    const int tid = threadIdx.x;
    const int wid = tid >> 5, lane = tid & 31;
    const int g = lane >> 2, tig = lane & 3;
    const int mt = wid & 3;          // 16-row tile
    const int nh = wid >> 2;         // 96-col half
    const int grp = lane >> 3;
    const unsigned lm_off = (unsigned)(((grp >> 1) * 8 + (lane & 7)) * 48 + (grp & 1) * 16);
    const int it_n[3]  = {(tid) % 192, (tid + 256) % 192, (tid + 512) % 192};
    const int it_hf[3] = {((tid) / 192) & 1, ((tid + 256) / 192) & 1, ((tid + 512) / 192) & 1};
    const int it_hl[3] = {((tid) / 192) >> 1, ((tid + 256) / 192) >> 1, ((tid + 512) / 192) >> 1};

    float acc[12][4];
    #pragma unroll
    for (int t = 0; t < 12; t++) { acc[t][0]=acc[t][1]=acc[t][2]=acc[t][3]=0.f; }

    // stage k-panel 0 into buf 0
    #pragma unroll
    for (int i = 0; i < 3; i++) {
        const __nv_bfloat16* src = (it_hl[i] ? Wlo : Whi) + it_n[i] * 192 + it_hf[i] * 8;
        float4 v = *reinterpret_cast<const float4*>(src);
        *reinterpret_cast<float4*>(wst + it_hl[i] * 9216 + it_n[i] * 48 + it_hf[i] * 16) = v;
    }
    __syncthreads();

    for (int k = 0; k < 12; k++) {
        const int buf = k & 1;
        float4 pf[3];
        if (k < 11) {
            #pragma unroll
            for (int i = 0; i < 3; i++) {
                const __nv_bfloat16* src = (it_hl[i] ? Wlo : Whi) + it_n[i] * 192
                                           + (k + 1) * 16 + it_hf[i] * 8;
                pf[i] = *reinterpret_cast<const float4*>(src);
            }
        }
        unsigned ahi[4], alo[4];
        {
            const int r0 = mt * 16 + g;
            const int kb = k * 16 + 2 * tig;
            ahi[0] = *(const unsigned*)&Ah[r0 * 200 + kb];
            ahi[1] = *(const unsigned*)&Ah[(r0 + 8) * 200 + kb];
            ahi[2] = *(const unsigned*)&Ah[r0 * 200 + kb + 8];
            ahi[3] = *(const unsigned*)&Ah[(r0 + 8) * 200 + kb + 8];
            alo[0] = *(const unsigned*)&Al[r0 * 200 + kb];
            alo[1] = *(const unsigned*)&Al[(r0 + 8) * 200 + kb];
            alo[2] = *(const unsigned*)&Al[r0 * 200 + kb + 8];
            alo[3] = *(const unsigned*)&Al[(r0 + 8) * 200 + kb + 8];
        }
        const unsigned base_h = wst_u32 + (unsigned)(buf * 18432) + lm_off;
        #pragma unroll
        for (int p = 0; p < 6; p++) {
            unsigned bh[4], bl[4];
            unsigned ad = base_h + (unsigned)((nh * 96 + 16 * p) * 48);
            ldsm4(bh, ad);
            ldsm4(bl, ad + 9216);
            mma_bf16(acc[2 * p], ahi, bh);
            mma_bf16(acc[2 * p], ahi, bl);
            mma_bf16(acc[2 * p], alo, bh);
            mma_bf16(acc[2 * p + 1], ahi, bh + 2);
            mma_bf16(acc[2 * p + 1], ahi, bl + 2);
            mma_bf16(acc[2 * p + 1], alo, bh + 2);
        }
        if (k < 11) {
            #pragma unroll
            for (int i = 0; i < 3; i++)
                *reinterpret_cast<float4*>(wst + (buf ^ 1) * 18432 + it_hl[i] * 9216
                                           + it_n[i] * 48 + it_hf[i] * 16) = pf[i];
            __syncthreads();
        }
    }

    const int r0 = mt * 16 + g, r1 = r0 + 8;
    #pragma unroll
    for (int t = 0; t < 12; t++) {
        int col = nh * 96 + t * 8 + 2 * tig;
        float2 bb = *reinterpret_cast<const float2*>(&bias[col]);
        if (r0 < 49) {
            float2 o = make_float2((acc[t][0] + bb.x) * scale, (acc[t][1] + bb.y) * scale);
            *reinterpret_cast<float2*>(&outp[r0 * 192 + col]) = o;
        }
        if (r1 < 49) {
            float2 o = make_float2((acc[t][2] + bb.x) * scale, (acc[t][3] + bb.y) * scale);
            *reinterpret_cast<float2*>(&outp[r1 * 192 + col]) = o;
        }
    }
}

__global__ void __launch_bounds__(THREADS, 1)
swin_fused_kernel(const float* __restrict__ x,
                  const float* __restrict__ mask,
                  const float* __restrict__ qkv_b,
                  const float* __restrict__ proj_b,
                  const float* __restrict__ rope,
                  float* __restrict__ out)
{
    extern __shared__ char smem[];
    __nv_bfloat16* Ah = (__nv_bfloat16*)(smem + AHI_OFF);
    __nv_bfloat16* Al = (__nv_bfloat16*)(smem + ALO_OFF);
    float* Qs = (float*)(smem + Q_OFF);
    float* Ks = (float*)(smem + K_OFF);
    float* Vs = (float*)(smem + V_OFF);
    float* LG = (float*)(smem + LG_OFF);
    const int tid = threadIdx.x;
    const int b = blockIdx.x;

    for (int i = tid; i < 4704; i += THREADS) {
        int n = i / 96, c = i % 96;
        float2 v = *reinterpret_cast<const float2*>(&x[(size_t)b * 9408 + n * 192 + 2 * c]);
        __nv_bfloat16 h0 = __float2bfloat16(v.x), h1 = __float2bfloat16(v.y);
        __nv_bfloat16 l0 = __float2bfloat16(v.x - __bfloat162float(h0));
        __nv_bfloat16 l1 = __float2bfloat16(v.y - __bfloat162float(h1));
        *(unsigned*)&Ah[n * 200 + 2 * c] = pkbf(h0, h1);
        *(unsigned*)&Al[n * 200 + 2 * c] = pkbf(l0, l1);
    }
    for (int i = tid; i < 15 * 96; i += THREADS) {
        int r = 49 + i / 96, c = i % 96;
        *(unsigned*)&Ah[r * 200 + 2 * c] = 0u;
        *(unsigned*)&Al[r * 200 + 2 * c] = 0u;
    }
    __syncthreads();

    gemm_mma(g_Whi,         g_Wlo,         qkv_b,       0.17677669529663687f, Qs);
    gemm_mma(g_Whi + 36864, g_Wlo + 36864, qkv_b + 192, 1.0f, Ks);
    gemm_mma(g_Whi + 73728, g_Wlo + 73728, qkv_b + 384, 1.0f, Vs);
    __syncthreads();

    for (int i = tid; i < 4704; i += THREADS) {
        int d = i & 15, nhh = i >> 4;
        int hh = nhh % 6, n = nhh / 6;
        float fx = rope[hh * 16 + d];
        float fy = rope[96 + hh * 16 + d];
        float ang = (float)(n % 7) * fx + (float)(n / 7) * fy;
        float sv, cv;
        sincosf(ang, &sv, &cv);
        int base = n * 192 + hh * 32 + 2 * d;
        float2 qu = *reinterpret_cast<float2*>(&Qs[base]);
        float2 ku = *reinterpret_cast<float2*>(&Ks[base]);
        *reinterpret_cast<float2*>(&Qs[base]) =
            make_float2(qu.x * cv - qu.y * sv, qu.x * sv + qu.y * cv);
        *reinterpret_cast<float2*>(&Ks[base]) =
            make_float2(ku.x * cv - ku.y * sv, ku.x * sv + ku.y * cv);
    }

    const float* mrow = mask + (size_t)(b & 63) * 2401;

    for (int hh = 0; hh < 6; hh++) {
        __syncthreads();
        for (int bi = tid; bi < 625; bi += THREADS) {
            int ni = (bi / 25) * 2, mi = (bi % 25) * 2;
            const float4* q0 = reinterpret_cast<const float4*>(&Qs[ni * 192 + hh * 32]);
            const float4* q1 = reinterpret_cast<const float4*>(&Qs[(ni + 1) * 192 + hh * 32]);
            const float4* k0 = reinterpret_cast<const float4*>(&Ks[mi * 192 + hh * 32]);
            const float4* k1 = reinterpret_cast<const float4*>(&Ks[(mi + 1) * 192 + hh * 32]);
            float a00 = 0.f, a01 = 0.f, a10 = 0.f, a11 = 0.f;
            #pragma unroll
            for (int d4 = 0; d4 < 8; d4++) {
                float4 qa = q0[d4], qb = q1[d4], ka = k0[d4], kb = k1[d4];
                a00 += qa.x * ka.x + qa.y * ka.y + qa.z * ka.z + qa.w * ka.w;
                a01 += qa.x * kb.x + qa.y * kb.y + qa.z * kb.z + qa.w * kb.w;
                a10 += qb.x * ka.x + qb.y * ka.y + qb.z * ka.z + qb.w * ka.w;
                a11 += qb.x * kb.x + qb.y * kb.y + qb.z * kb.z + qb.w * kb.w;
            }
            bool n1ok = (ni + 1) < 49, m1ok = (mi + 1) < 49;
            LG[ni * LG_STRIDE + mi] = a00 + mrow[ni * 49 + mi];
            if (m1ok)         LG[ni * LG_STRIDE + mi + 1]       = a01 + mrow[ni * 49 + mi + 1];
            if (n1ok)         LG[(ni + 1) * LG_STRIDE + mi]     = a10 + mrow[(ni + 1) * 49 + mi];
            if (n1ok && m1ok) LG[(ni + 1) * LG_STRIDE + mi + 1] = a11 + mrow[(ni + 1) * 49 + mi + 1];
        }
        __syncthreads();
        if (tid < 49) {
            float* row = &LG[tid * LG_STRIDE];
            float mx = row[0];
            #pragma unroll 7
            for (int m = 1; m < 49; m++) mx = fmaxf(mx, row[m]);
            float s = 0.f;
            #pragma unroll 7
            for (int m = 0; m < 49; m++) { float e = __expf(row[m] - mx); row[m] = e; s += e; }
            float inv = 1.0f / s;
            #pragma unroll 7
            for (int m = 0; m < 49; m++) row[m] *= inv;
        }
        __syncthreads();
        {
            int dp = tid & 15, nb = tid >> 4;
            #pragma unroll
            for (int t = 0; t < 4; t++) {
                int n = nb + 16 * t;
                if (n < 49) {
                    unsigned long long accv = 0ULL;
                    const float* pr = &LG[n * LG_STRIDE];
                    const float* vp = &Vs[hh * 32 + 2 * dp];
                    #pragma unroll 7
                    for (int m = 0; m < 49; m++) {
                        unsigned long long p2 = pk2(pr[m], pr[m]);
                        fma2(accv, p2,
                             *reinterpret_cast<const unsigned long long*>(&vp[m * 192]));
                    }
                    float2 r = unpk2(accv);
                    __nv_bfloat16 h0 = __float2bfloat16(r.x), h1 = __float2bfloat16(r.y);
                    __nv_bfloat16 l0 = __float2bfloat16(r.x - __bfloat162float(h0));
                    __nv_bfloat16 l1 = __float2bfloat16(r.y - __bfloat162float(h1));
                    int cc = hh * 32 + 2 * dp;
                    *(unsigned*)&Ah[n * 200 + cc] = pkbf(h0, h1);
                    *(unsigned*)&Al[n * 200 + cc] = pkbf(l0, l1);
                }
            }
        }
    }

    gemm_mma(g_Phi, g_Plo, proj_b, 1.0f, out + (size_t)b * 9408);
}

extern "C" void kernel_launch(void* const* d_in, const int* in_sizes, int n_in,
                              void* d_out, int out_size) {
    const float* x      = (const float*)d_in[0];
    const float* mask   = (const float*)d_in[1];
    const float* qkv_w  = (const float*)d_in[2];
    const float* qkv_b  = (const float*)d_in[3];
    const float* proj_w = (const float*)d_in[4];
    const float* proj_b = (const float*)d_in[5];
    const float* rope   = (const float*)d_in[6];
    float* out = (float*)d_out;

    prep_weights<<<432, 256>>>(qkv_w, proj_w);
    cudaFuncSetAttribute(swin_fused_kernel,
                         cudaFuncAttributeMaxDynamicSharedMemorySize, SMEM_BYTES);
    swin_fused_kernel<<<4096, THREADS, SMEM_BYTES>>>(
        x, mask, qkv_b, proj_b, rope, out);
}

// round 6
// speedup vs baseline: 1.3164x; 1.3164x over previous
#include <cuda_runtime.h>
#include <cuda_bf16.h>

#define THREADS 256
// ---- smem byte offsets ----
#define AHI_OFF 0          // x / attn-out hi  [64][200] bf16
#define ALO_OFF 25600      // lo
#define WST_OFF 51200      // W stage [2][2][192][48B]   (aliases LG)
#define LG_OFF  51200      // logits [49][52] f32
#define QHI_OFF 88064      // [64][196] bf16
#define QLO_OFF 113152
#define KHI_OFF 138240
#define KLO_OFF 163328
#define CSV_OFF 188416     // cos/sin [49][96] float2  -> later V [49][192] f32
#define SMEM_BYTES 226048
#define QSTR 196
#define LG_STRIDE 52

__device__ __nv_bfloat16 g_Whi[110592];
__device__ __nv_bfloat16 g_Wlo[110592];
__device__ __nv_bfloat16 g_Phi[36864];
__device__ __nv_bfloat16 g_Plo[36864];

__global__ void prep_weights(const float* __restrict__ qkv_w,
                             const float* __restrict__ proj_w) {
    int i = blockIdx.x * 256 + threadIdx.x;
    if (i < 110592) {
        float v = qkv_w[i];
        __nv_bfloat16 h = __float2bfloat16(v);
        g_Whi[i] = h;
        g_Wlo[i] = __float2bfloat16(v - __bfloat162float(h));
    }
    if (i < 36864) {
        float v = proj_w[i];
        __nv_bfloat16 h = __float2bfloat16(v);
        g_Phi[i] = h;
        g_Plo[i] = __float2bfloat16(v - __bfloat162float(h));
    }
}

__device__ __forceinline__ unsigned long long pk2(float lo, float hi) {
    unsigned long long r;
    asm("mov.b64 %0, {%1, %2};" : "=l"(r) : "f"(lo), "f"(hi));
    return r;
}
__device__ __forceinline__ float2 unpk2(unsigned long long v) {
    float2 r;
    asm("mov.b64 {%0, %1}, %2;" : "=f"(r.x), "=f"(r.y) : "l"(v));
    return r;
}
__device__ __forceinline__ void fma2(unsigned long long& d, unsigned long long a,
                                     unsigned long long b) {
    asm("fma.rn.f32x2 %0, %1, %2, %0;" : "+l"(d) : "l"(a), "l"(b));
}
__device__ __forceinline__ unsigned pkbf(__nv_bfloat16 a, __nv_bfloat16 b) {
    return (unsigned)__bfloat16_as_ushort(a) | ((unsigned)__bfloat16_as_ushort(b) << 16);
}
__device__ __forceinline__ void mma_bf16(float* c, const unsigned* a, const unsigned* b) {
    asm volatile(
        "mma.sync.aligned.m16n8k16.row.col.f32.bf16.bf16.f32 "
        "{%0,%1,%2,%3}, {%4,%5,%6,%7}, {%8,%9}, {%0,%1,%2,%3};\n"
        : "+f"(c[0]), "+f"(c[1]), "+f"(c[2]), "+f"(c[3])
        : "r"(a[0]), "r"(a[1]), "r"(a[2]), "r"(a[3]), "r"(b[0]), "r"(b[1]));
}
__device__ __forceinline__ void ldsm4(unsigned* r, unsigned addr) {
    asm volatile("ldmatrix.sync.aligned.m8n8.x4.shared.b16 {%0,%1,%2,%3}, [%4];\n"
                 : "=r"(r[0]), "=r"(r[1]), "=r"(r[2]), "=r"(r[3]) : "r"(addr));
}

// C[49][192] = A(hi+lo)[64][192] @ W^T + bias (scaled).
// MODE 0: fp32 store to outp (stride 192).  MODE 1: RoPE then bf16 hi/lo to ohi/olo.
template <int MODE>
__device__ __noinline__ void gemm_mma(const __nv_bfloat16* __restrict__ Whi,
                                      const __nv_bfloat16* __restrict__ Wlo,
                                      const float* __restrict__ bias, float scale,
                                      float* __restrict__ outp,
                                      __nv_bfloat16* __restrict__ ohi,
                                      __nv_bfloat16* __restrict__ olo) {
    extern __shared__ char smem[];
    const __nv_bfloat16* Ah = (const __nv_bfloat16*)(smem + AHI_OFF);
    const __nv_bfloat16* Al = (const __nv_bfloat16*)(smem + ALO_OFF);
    const float2* CS = (const float2*)(smem + CSV_OFF);
    char* wst = smem + WST_OFF;
    const unsigned wst_u32 = (unsigned)__cvta_generic_to_shared(wst);

    const int tid = threadIdx.x;
    const int wid = tid >> 5, lane = tid & 31;
    const int g = lane >> 2, tig = lane & 3;
    const int mt = wid & 3;
    const int nh = wid >> 2;
    const int grp = lane >> 3;
    const unsigned lm_off = (unsigned)(((grp >> 1) * 8 + (lane & 7)) * 48 + (grp & 1) * 16);
    const int it_n[3]  = {(tid) % 192, (tid + 256) % 192, (tid + 512) % 192};
    const int it_hf[3] = {((tid) / 192) & 1, ((tid + 256) / 192) & 1, ((tid + 512) / 192) & 1};
    const int it_hl[3] = {((tid) / 192) >> 1, ((tid + 256) / 192) >> 1, ((tid + 512) / 192) >> 1};

    float acc[12][4];
    #pragma unroll
    for (int t = 0; t < 12; t++) { acc[t][0]=acc[t][1]=acc[t][2]=acc[t][3]=0.f; }

    #pragma unroll
    for (int i = 0; i < 3; i++) {
        const __nv_bfloat16* src = (it_hl[i] ? Wlo : Whi) + it_n[i] * 192 + it_hf[i] * 8;
        float4 v = *reinterpret_cast<const float4*>(src);
        *reinterpret_cast<float4*>(wst + it_hl[i] * 9216 + it_n[i] * 48 + it_hf[i] * 16) = v;
    }
    __syncthreads();

    for (int k = 0; k < 12; k++) {
        const int buf = k & 1;
        float4 pf[3];
        if (k < 11) {
            #pragma unroll
            for (int i = 0; i < 3; i++) {
                const __nv_bfloat16* src = (it_hl[i] ? Wlo : Whi) + it_n[i] * 192
                                           + (k + 1) * 16 + it_hf[i] * 8;
                pf[i] = *reinterpret_cast<const float4*>(src);
            }
        }
        unsigned ahi[4], alo[4];
        {
            const int r0 = mt * 16 + g;
            const int kb = k * 16 + 2 * tig;
            ahi[0] = *(const unsigned*)&Ah[r0 * 200 + kb];
            ahi[1] = *(const unsigned*)&Ah[(r0 + 8) * 200 + kb];
            ahi[2] = *(const unsigned*)&Ah[r0 * 200 + kb + 8];
            ahi[3] = *(const unsigned*)&Ah[(r0 + 8) * 200 + kb + 8];
            alo[0] = *(const unsigned*)&Al[r0 * 200 + kb];
            alo[1] = *(const unsigned*)&Al[(r0 + 8) * 200 + kb];
            alo[2] = *(const unsigned*)&Al[r0 * 200 + kb + 8];
            alo[3] = *(const unsigned*)&Al[(r0 + 8) * 200 + kb + 8];
        }
        const unsigned base_h = wst_u32 + (unsigned)(buf * 18432) + lm_off;
        #pragma unroll
        for (int p = 0; p < 6; p++) {
            unsigned bh[4], bl[4];
            unsigned ad = base_h + (unsigned)((nh * 96 + 16 * p) * 48);
            ldsm4(bh, ad);
            ldsm4(bl, ad + 9216);
            mma_bf16(acc[2 * p], ahi, bh);
            mma_bf16(acc[2 * p], ahi, bl);
            mma_bf16(acc[2 * p], alo, bh);
            mma_bf16(acc[2 * p + 1], ahi, bh + 2);
            mma_bf16(acc[2 * p + 1], ahi, bl + 2);
            mma_bf16(acc[2 * p + 1], alo, bh + 2);
        }
        if (k < 11) {
            #pragma unroll
            for (int i = 0; i < 3; i++)
                *reinterpret_cast<float4*>(wst + (buf ^ 1) * 18432 + it_hl[i] * 9216
                                           + it_n[i] * 48 + it_hf[i] * 16) = pf[i];
            __syncthreads();
        }
    }

    const int r0 = mt * 16 + g, r1 = r0 + 8;
    #pragma unroll
    for (int t = 0; t < 12; t++) {
        const int col = nh * 96 + t * 8 + 2 * tig;
        float2 bb = *reinterpret_cast<const float2*>(&bias[col]);
        #pragma unroll
        for (int half = 0; half < 2; half++) {
            const int r = half ? r1 : r0;
            if (r < 49) {
                float vx = (acc[t][half * 2 + 0] + bb.x) * scale;
                float vy = (acc[t][half * 2 + 1] + bb.y) * scale;
                if (MODE == 0) {
                    *reinterpret_cast<float2*>(&outp[r * 192 + col]) = make_float2(vx, vy);
                } else {
                    float2 cs = CS[r * 96 + (col >> 1)];
                    float re = vx * cs.x - vy * cs.y;
                    float im = vx * cs.y + vy * cs.x;
                    __nv_bfloat16 h0 = __float2bfloat16(re), h1 = __float2bfloat16(im);
                    __nv_bfloat16 l0 = __float2bfloat16(re - __bfloat162float(h0));
                    __nv_bfloat16 l1 = __float2bfloat16(im - __bfloat162float(h1));
                    *(unsigned*)&ohi[r * QSTR + col] = pkbf(h0, h1);
                    *(unsigned*)&olo[r * QSTR + col] = pkbf(l0, l1);
                }
            }
        }
    }
}

__global__ void __launch_bounds__(THREADS, 1)
swin_fused_kernel(const float* __restrict__ x,
                  const float* __restrict__ mask,
                  const float* __restrict__ qkv_b,
                  const float* __restrict__ proj_b,
                  const float* __restrict__ rope,
                  float* __restrict__ out)
{
    extern __shared__ char smem[];
    __nv_bfloat16* Ah  = (__nv_bfloat16*)(smem + AHI_OFF);
    __nv_bfloat16* Al  = (__nv_bfloat16*)(smem + ALO_OFF);
    __nv_bfloat16* Qhi = (__nv_bfloat16*)(smem + QHI_OFF);
    __nv_bfloat16* Qlo = (__nv_bfloat16*)(smem + QLO_OFF);
    __nv_bfloat16* Khi = (__nv_bfloat16*)(smem + KHI_OFF);
    __nv_bfloat16* Klo = (__nv_bfloat16*)(smem + KLO_OFF);
    float2* CSf2 = (float2*)(smem + CSV_OFF);
    float*  Vs   = (float*)(smem + CSV_OFF);
    float*  LG   = (float*)(smem + LG_OFF);
    const int tid = threadIdx.x;
    const int b = blockIdx.x;
    const int lane = tid & 31, wid = tid >> 5;
    const int g = lane >> 2, tig = lane & 3;

    // x -> bf16 hi/lo
    for (int i = tid; i < 4704; i += THREADS) {
        int n = i / 96, c = i % 96;
        float2 v = *reinterpret_cast<const float2*>(&x[(size_t)b * 9408 + n * 192 + 2 * c]);
        __nv_bfloat16 h0 = __float2bfloat16(v.x), h1 = __float2bfloat16(v.y);
        __nv_bfloat16 l0 = __float2bfloat16(v.x - __bfloat162float(h0));
        __nv_bfloat16 l1 = __float2bfloat16(v.y - __bfloat162float(h1));
        *(unsigned*)&Ah[n * 200 + 2 * c] = pkbf(h0, h1);
        *(unsigned*)&Al[n * 200 + 2 * c] = pkbf(l0, l1);
    }
    for (int i = tid; i < 15 * 96; i += THREADS) {
        int r = 49 + i / 96, c = i % 96;
        *(unsigned*)&Ah[r * 200 + 2 * c] = 0u;
        *(unsigned*)&Al[r * 200 + 2 * c] = 0u;
    }
    // cos/sin table [49][96]
    for (int i = tid; i < 4704; i += THREADS) {
        int cp = i % 96, n = i / 96;
        int hh = cp >> 4, d = cp & 15;
        float fx = rope[hh * 16 + d];
        float fy = rope[96 + hh * 16 + d];
        float ang = (float)(n % 7) * fx + (float)(n / 7) * fy;
        float sv, cv;
        sincosf(ang, &sv, &cv);
        CSf2[i] = make_float2(cv, sv);
    }
    // no explicit sync needed: gemm_mma's internal first sync orders the fills

    gemm_mma<1>(g_Whi,         g_Wlo,         qkv_b,       0.17677669529663687f,
                nullptr, Qhi, Qlo);
    gemm_mma<1>(g_Whi + 36864, g_Wlo + 36864, qkv_b + 192, 1.0f, nullptr, Khi, Klo);
    gemm_mma<0>(g_Whi + 73728, g_Wlo + 73728, qkv_b + 384, 1.0f, Vs, nullptr, nullptr);

    const float* mrow = mask + (size_t)(b & 63) * 2401;
    const int mt = wid & 3, ngrp = wid >> 2;
    const int ntn = ngrp ? 3 : 4;
    const int nt0 = ngrp * 4;

    for (int hh = 0; hh < 6; hh++) {
        __syncthreads();   // V ready (hh=0) / prev P@V done reading LG
        // ---- logits via 3-pass split-bf16 MMA ----
        {
            float c[4][4];
            #pragma unroll
            for (int t = 0; t < 4; t++) { c[t][0]=c[t][1]=c[t][2]=c[t][3]=0.f; }
            const int hb = hh * 32;
            const int r0 = mt * 16 + g;
            #pragma unroll
            for (int pass = 0; pass < 3; pass++) {
                const __nv_bfloat16* Ap = (pass == 2) ? Qlo : Qhi;
                const __nv_bfloat16* Bp = (pass == 1) ? Klo : Khi;
                #pragma unroll
                for (int kc = 0; kc < 2; kc++) {
                    const int kb = hb + kc * 16 + 2 * tig;
                    unsigned a[4];
                    a[0] = *(const unsigned*)&Ap[r0 * QSTR + kb];
                    a[1] = *(const unsigned*)&Ap[(r0 + 8) * QSTR + kb];
                    a[2] = *(const unsigned*)&Ap[r0 * QSTR + kb + 8];
                    a[3] = *(const unsigned*)&Ap[(r0 + 8) * QSTR + kb + 8];
                    #pragma unroll
                    for (int t = 0; t < 4; t++) {
                        if (t < ntn) {
                            const int nr = (nt0 + t) * 8 + g;
                            unsigned bfr[2];
                            bfr[0] = *(const unsigned*)&Bp[nr * QSTR + kb];
                            bfr[1] = *(const unsigned*)&Bp[nr * QSTR + kb + 8];
                            mma_bf16(c[t], a, bfr);
                        }
                    }
                }
            }
            #pragma unroll
            for (int t = 0; t < 4; t++) {
                if (t < ntn) {
                    const int col = (nt0 + t) * 8 + 2 * tig;
                    #pragma unroll
                    for (int half = 0; half < 2; half++) {
                        const int r = r0 + half * 8;
                        if (r < 49) {
                            if (col < 49)
                                LG[r * LG_STRIDE + col] = c[t][half * 2] + mrow[r * 49 + col];
                            if (col + 1 < 49)
                                LG[r * LG_STRIDE + col + 1] = c[t][half * 2 + 1]
                                                              + mrow[r * 49 + col + 1];
                        }
                    }
                }
            }
        }
        __syncthreads();
        // ---- warp-parallel softmax ----
        for (int r = wid; r < 49; r += 8) {
            float* row = &LG[r * LG_STRIDE];
            float v0 = row[lane];
            bool ok1 = (lane + 32) < 49;
            float v1 = ok1 ? row[lane + 32] : -3.0e38f;
            float mx = fmaxf(v0, v1);
            #pragma unroll
            for (int o = 16; o; o >>= 1) mx = fmaxf(mx, __shfl_xor_sync(~0u, mx, o));
            float e0 = __expf(v0 - mx);
            float e1 = ok1 ? __expf(v1 - mx) : 0.f;
            float s = e0 + e1;
            #pragma unroll
            for (int o = 16; o; o >>= 1) s += __shfl_xor_sync(~0u, s, o);
            float inv = 1.0f / s;
            row[lane] = e0 * inv;
            if (ok1) row[lane + 32] = e1 * inv;
        }
        __syncthreads();
        // ---- P @ V (scalar f32x2) -> bf16 split into Ah/Al ----
        {
            int dp = tid & 15, nb = tid >> 4;
            #pragma unroll
            for (int t = 0; t < 4; t++) {
                int n = nb + 16 * t;
                if (n < 49) {
                    unsigned long long accv = 0ULL;
                    const float* pr = &LG[n * LG_STRIDE];
                    const float* vp = &Vs[hh * 32 + 2 * dp];
                    #pragma unroll 7
                    for (int m = 0; m < 49; m++) {
                        unsigned long long p2 = pk2(pr[m], pr[m]);
                        fma2(accv, p2,
                             *reinterpret_cast<const unsigned long long*>(&vp[m * 192]));
                    }
                    float2 r = unpk2(accv);
                    __nv_bfloat16 h0 = __float2bfloat16(r.x), h1 = __float2bfloat16(r.y);
                    __nv_bfloat16 l0 = __float2bfloat16(r.x - __bfloat162float(h0));
                    __nv_bfloat16 l1 = __float2bfloat16(r.y - __bfloat162float(h1));
                    int cc = hh * 32 + 2 * dp;
                    *(unsigned*)&Ah[n * 200 + cc] = pkbf(h0, h1);
                    *(unsigned*)&Al[n * 200 + cc] = pkbf(l0, l1);
                }
            }
        }
    }
    __syncthreads();  // P@V LG reads done before proj stages over LG region

    gemm_mma<0>(g_Phi, g_Plo, proj_b, 1.0f, out + (size_t)b * 9408, nullptr, nullptr);
}

extern "C" void kernel_launch(void* const* d_in, const int* in_sizes, int n_in,
                              void* d_out, int out_size) {
    const float* x      = (const float*)d_in[0];
    const float* mask   = (const float*)d_in[1];
    const float* qkv_w  = (const float*)d_in[2];
    const float* qkv_b  = (const float*)d_in[3];
    const float* proj_w = (const float*)d_in[4];
    const float* proj_b = (const float*)d_in[5];
    const float* rope   = (const float*)d_in[6];
    float* out = (float*)d_out;

    prep_weights<<<432, 256>>>(qkv_w, proj_w);
    cudaFuncSetAttribute(swin_fused_kernel,
                         cudaFuncAttributeMaxDynamicSharedMemorySize, SMEM_BYTES);
    swin_fused_kernel<<<4096, THREADS, SMEM_BYTES>>>(
        x, mask, qkv_b, proj_b, rope, out);
}

// round 7
// speedup vs baseline: 1.5756x; 1.1969x over previous
#include <cuda_runtime.h>
#include <cuda_bf16.h>

#define THREADS 512
// ---- smem byte offsets ----
#define AHI_OFF 0          // x / attn-out hi [64][200] bf16
#define ALO_OFF 25600
#define WST_OFF 51200      // W stage [2buf][2hl][192][48B] = 36864  (aliases LG)
#define LG_OFF  51200      // logits [64][68] f32 (zero padded)
#define LGS     68
#define QHI_OFF 88064      // [64][196] bf16
#define QLO_OFF 113152
#define KHI_OFF 138240     // [56][196] bf16
#define KLO_OFF 160192
#define VTH_OFF 182144     // V^T [192][64] bf16, XOR-swizzled tokens
#define VTL_OFF 206720
#define RT_OFF  231296     // rope freqs copy, 192 floats
#define SMEM_BYTES 232064
#define QSTR 196

__device__ __nv_bfloat16 g_Whi[110592];
__device__ __nv_bfloat16 g_Wlo[110592];
__device__ __nv_bfloat16 g_Phi[36864];
__device__ __nv_bfloat16 g_Plo[36864];

__global__ void prep_weights(const float* __restrict__ qkv_w,
                             const float* __restrict__ proj_w) {
    int i = blockIdx.x * 256 + threadIdx.x;
    if (i < 110592) {
        float v = qkv_w[i];
        __nv_bfloat16 h = __float2bfloat16(v);
        g_Whi[i] = h;
        g_Wlo[i] = __float2bfloat16(v - __bfloat162float(h));
    }
    if (i < 36864) {
        float v = proj_w[i];
        __nv_bfloat16 h = __float2bfloat16(v);
        g_Phi[i] = h;
        g_Plo[i] = __float2bfloat16(v - __bfloat162float(h));
    }
}

__device__ __forceinline__ unsigned pkbf(__nv_bfloat16 a, __nv_bfloat16 b) {
    return (unsigned)__bfloat16_as_ushort(a) | ((unsigned)__bfloat16_as_ushort(b) << 16);
}
// split two floats into packed bf16 hi + packed bf16 lo(residual)
__device__ __forceinline__ void split2(float x, float y, unsigned& hi, unsigned& lo) {
    __nv_bfloat16 h0 = __float2bfloat16(x), h1 = __float2bfloat16(y);
    __nv_bfloat16 l0 = __float2bfloat16(x - __bfloat162float(h0));
    __nv_bfloat16 l1 = __float2bfloat16(y - __bfloat162float(h1));
    hi = pkbf(h0, h1);
    lo = pkbf(l0, l1);
}
__device__ __forceinline__ void mma_bf16(float* c, const unsigned* a, const unsigned* b) {
    asm volatile(
        "mma.sync.aligned.m16n8k16.row.col.f32.bf16.bf16.f32 "
        "{%0,%1,%2,%3}, {%4,%5,%6,%7}, {%8,%9}, {%0,%1,%2,%3};\n"
        : "+f"(c[0]), "+f"(c[1]), "+f"(c[2]), "+f"(c[3])
        : "r"(a[0]), "r"(a[1]), "r"(a[2]), "r"(a[3]), "r"(b[0]), "r"(b[1]));
}
__device__ __forceinline__ void ldsm4(unsigned* r, unsigned addr) {
    asm volatile("ldmatrix.sync.aligned.m8n8.x4.shared.b16 {%0,%1,%2,%3}, [%4];\n"
                 : "=r"(r[0]), "=r"(r[1]), "=r"(r[2]), "=r"(r[3]) : "r"(addr));
}
// V^T element index: [dim][token], token XOR-swizzled for conflict-free LDS
__device__ __forceinline__ int vt_idx(int dim, int tok) {
    return dim * 64 + (tok ^ ((dim & 7) << 3));
}

// C[49][192] = A(hi+lo)[64][192] @ W^T + bias (scaled).  16-warp version.
// MODE 0: fp32 -> outp (stride 192).  MODE 1: RoPE -> bf16 hi/lo (ohi/olo, stride QSTR).
// MODE 2: transposed swizzled bf16 hi/lo -> ohi/olo (= Vthi/Vtlo).
template <int MODE>
__device__ __noinline__ void gemm_mma(const __nv_bfloat16* __restrict__ Whi,
                                      const __nv_bfloat16* __restrict__ Wlo,
                                      const float* __restrict__ bias, float scale,
                                      float* __restrict__ outp,
                                      __nv_bfloat16* __restrict__ ohi,
                                      __nv_bfloat16* __restrict__ olo) {
    extern __shared__ char smem[];
    const __nv_bfloat16* Ah = (const __nv_bfloat16*)(smem + AHI_OFF);
    const __nv_bfloat16* Al = (const __nv_bfloat16*)(smem + ALO_OFF);
    const float* RT = (const float*)(smem + RT_OFF);
    char* wst = smem + WST_OFF;
    const unsigned wst_u32 = (unsigned)__cvta_generic_to_shared(wst);

    const int tid = threadIdx.x;
    const int wid = tid >> 5, lane = tid & 31;
    const int g = lane >> 2, tig = lane & 3;
    const int mt = wid & 3;          // 16-row tile
    const int nq = wid >> 2;         // 48-col quarter
    const int grp = lane >> 3;
    const unsigned lm_off = (unsigned)(((grp >> 1) * 8 + (lane & 7)) * 48 + (grp & 1) * 16);

    const int n0 = tid % 192, q0 = tid / 192;
    const int hf0 = q0 & 1, hl0 = q0 >> 1;
    const int i1 = tid + 512;
    const bool pr1 = tid < 256;
    const int n1 = i1 % 192, q1 = i1 / 192;
    const int hf1 = q1 & 1, hl1 = q1 >> 1;

    float acc[6][4];
    #pragma unroll
    for (int t = 0; t < 6; t++) { acc[t][0]=acc[t][1]=acc[t][2]=acc[t][3]=0.f; }

    // stage k-panel 0 into buf 0
    {
        float4 v = *reinterpret_cast<const float4*>((hl0 ? Wlo : Whi) + n0 * 192 + hf0 * 8);
        *reinterpret_cast<float4*>(wst + hl0 * 9216 + n0 * 48 + hf0 * 16) = v;
        if (pr1) {
            float4 w = *reinterpret_cast<const float4*>((hl1 ? Wlo : Whi) + n1 * 192 + hf1 * 8);
            *reinterpret_cast<float4*>(wst + hl1 * 9216 + n1 * 48 + hf1 * 16) = w;
        }
    }
    __syncthreads();

    for (int k = 0; k < 12; k++) {
        const int buf = k & 1;
        float4 pf0, pf1;
        if (k < 11) {
            pf0 = *reinterpret_cast<const float4*>((hl0 ? Wlo : Whi) + n0 * 192
                                                   + (k + 1) * 16 + hf0 * 8);
            if (pr1)
                pf1 = *reinterpret_cast<const float4*>((hl1 ? Wlo : Whi) + n1 * 192
                                                       + (k + 1) * 16 + hf1 * 8);
        }
        unsigned ahi[4], alo[4];
        {
            const int r0 = mt * 16 + g;
            const int kb = k * 16 + 2 * tig;
            ahi[0] = *(const unsigned*)&Ah[r0 * 200 + kb];
            ahi[1] = *(const unsigned*)&Ah[(r0 + 8) * 200 + kb];
            ahi[2] = *(const unsigned*)&Ah[r0 * 200 + kb + 8];
            ahi[3] = *(const unsigned*)&Ah[(r0 + 8) * 200 + kb + 8];
            alo[0] = *(const unsigned*)&Al[r0 * 200 + kb];
            alo[1] = *(const unsigned*)&Al[(r0 + 8) * 200 + kb];
            alo[2] = *(const unsigned*)&Al[r0 * 200 + kb + 8];
            alo[3] = *(const unsigned*)&Al[(r0 + 8) * 200 + kb + 8];
        }
        const unsigned base_h = wst_u32 + (unsigned)(buf * 18432) + lm_off;
        #pragma unroll
        for (int p = 0; p < 3; p++) {
            unsigned bh[4], bl[4];
            unsigned ad = base_h + (unsigned)((nq * 48 + 16 * p) * 48);
            ldsm4(bh, ad);
            ldsm4(bl, ad + 9216);
            mma_bf16(acc[2 * p], ahi, bh);
            mma_bf16(acc[2 * p], ahi, bl);
            mma_bf16(acc[2 * p], alo, bh);
            mma_bf16(acc[2 * p + 1], ahi, bh + 2);
            mma_bf16(acc[2 * p + 1], ahi, bl + 2);
            mma_bf16(acc[2 * p + 1], alo, bh + 2);
        }
        if (k < 11) {
            *reinterpret_cast<float4*>(wst + (buf ^ 1) * 18432 + hl0 * 9216
                                       + n0 * 48 + hf0 * 16) = pf0;
            if (pr1)
                *reinterpret_cast<float4*>(wst + (buf ^ 1) * 18432 + hl1 * 9216
                                           + n1 * 48 + hf1 * 16) = pf1;
            __syncthreads();
        }
    }

    const int r0 = mt * 16 + g;
    #pragma unroll
    for (int t = 0; t < 6; t++) {
        const int col = nq * 48 + t * 8 + 2 * tig;
        float2 bb = *reinterpret_cast<const float2*>(&bias[col]);
        float fx, fy;
        if (MODE == 1) {
            int hh = col >> 5, d = (col & 31) >> 1;
            fx = RT[hh * 16 + d];
            fy = RT[96 + hh * 16 + d];
        }
        #pragma unroll
        for (int half = 0; half < 2; half++) {
            const int r = r0 + half * 8;
            if (r < 49) {
                float vx = (acc[t][half * 2 + 0] + bb.x) * scale;
                float vy = (acc[t][half * 2 + 1] + bb.y) * scale;
                if (MODE == 0) {
                    *reinterpret_cast<float2*>(&outp[r * 192 + col]) = make_float2(vx, vy);
                } else if (MODE == 1) {
                    float ang = (float)(r % 7) * fx + (float)(r / 7) * fy;
                    float sv, cv;
                    sincosf(ang, &sv, &cv);
                    float re = vx * cv - vy * sv;
                    float im = vx * sv + vy * cv;
                    unsigned hi, lo;
                    split2(re, im, hi, lo);
                    *(unsigned*)&ohi[r * QSTR + col] = hi;
                    *(unsigned*)&olo[r * QSTR + col] = lo;
                } else {
                    __nv_bfloat16 h0 = __float2bfloat16(vx);
                    __nv_bfloat16 l0 = __float2bfloat16(vx - __bfloat162float(h0));
                    __nv_bfloat16 h1 = __float2bfloat16(vy);
                    __nv_bfloat16 l1 = __float2bfloat16(vy - __bfloat162float(h1));
                    ohi[vt_idx(col, r)] = h0;
                    olo[vt_idx(col, r)] = l0;
                    ohi[vt_idx(col + 1, r)] = h1;
                    olo[vt_idx(col + 1, r)] = l1;
                }
            }
        }
    }
}

__global__ void __launch_bounds__(THREADS, 1)
swin_fused_kernel(const float* __restrict__ x,
                  const float* __restrict__ mask,
                  const float* __restrict__ qkv_b,
                  const float* __restrict__ proj_b,
                  const float* __restrict__ rope,
                  float* __restrict__ out)
{
    extern __shared__ char smem[];
    __nv_bfloat16* Ah   = (__nv_bfloat16*)(smem + AHI_OFF);
    __nv_bfloat16* Al   = (__nv_bfloat16*)(smem + ALO_OFF);
    __nv_bfloat16* Qhi  = (__nv_bfloat16*)(smem + QHI_OFF);
    __nv_bfloat16* Qlo  = (__nv_bfloat16*)(smem + QLO_OFF);
    __nv_bfloat16* Khi  = (__nv_bfloat16*)(smem + KHI_OFF);
    __nv_bfloat16* Klo  = (__nv_bfloat16*)(smem + KLO_OFF);
    __nv_bfloat16* Vthi = (__nv_bfloat16*)(smem + VTH_OFF);
    __nv_bfloat16* Vtlo = (__nv_bfloat16*)(smem + VTL_OFF);
    float* LG = (float*)(smem + LG_OFF);
    float* RT = (float*)(smem + RT_OFF);
    const int tid = threadIdx.x;
    const int b = blockIdx.x;
    const int lane = tid & 31, wid = tid >> 5;
    const int g = lane >> 2, tig = lane & 3;

    // ---- prologue: x -> bf16 hi/lo, pads, rope copy, zero V^T ----
    for (int i = tid; i < 4704; i += THREADS) {
        int n = i / 96, c = i % 96;
        float2 v = *reinterpret_cast<const float2*>(&x[(size_t)b * 9408 + n * 192 + 2 * c]);
        unsigned hi, lo;
        split2(v.x, v.y, hi, lo);
        *(unsigned*)&Ah[n * 200 + 2 * c] = hi;
        *(unsigned*)&Al[n * 200 + 2 * c] = lo;
    }
    for (int i = tid; i < 15 * 96; i += THREADS) {     // A pad rows 49..63
        int r = 49 + i / 96, c = i % 96;
        *(unsigned*)&Ah[r * 200 + 2 * c] = 0u;
        *(unsigned*)&Al[r * 200 + 2 * c] = 0u;
    }
    for (int i = tid; i < 7 * 98; i += THREADS) {      // K pad rows 49..55
        int r = 49 + i / 98, c = i % 98;
        *(unsigned*)&Khi[r * QSTR + 2 * c] = 0u;
        *(unsigned*)&Klo[r * QSTR + 2 * c] = 0u;
    }
    {   // zero V^T hi+lo (49152 B = 3072 float4)
        float4* vz = reinterpret_cast<float4*>(smem + VTH_OFF);
        for (int i = tid; i < 3072; i += THREADS) vz[i] = make_float4(0.f, 0.f, 0.f, 0.f);
    }
    if (tid < 192) RT[tid] = rope[tid];
    // gemm's first internal __syncthreads orders all the above fills

    gemm_mma<1>(g_Whi,         g_Wlo,         qkv_b,       0.17677669529663687f,
                nullptr, Qhi, Qlo);
    gemm_mma<1>(g_Whi + 36864, g_Wlo + 36864, qkv_b + 192, 1.0f, nullptr, Khi, Klo);
    gemm_mma<2>(g_Whi + 73728, g_Wlo + 73728, qkv_b + 384, 1.0f, nullptr, Vthi, Vtlo);
    __syncthreads();                 // WST reads done; now LG region is ours
    for (int i = tid; i < 64 * LGS; i += THREADS) LG[i] = 0.0f;

    const float* mrow = mask + (size_t)(b & 63) * 2401;
    const int mt = wid & 3;
    const int r0 = mt * 16 + g;

    for (int hh = 0; hh < 6; hh++) {
        __syncthreads();   // zero-LG / prev P@V LG-reads done
        // ---- logits = q_h @ k_h^T + mask (3-term split-bf16 MMA) ----
        {
            const int ng = wid >> 2;
            const int nt0 = ng * 2;
            const int ntn = (nt0 < 6) ? 2 : 1;   // 7 n-tiles over 4 groups
            float c[2][4];
            #pragma unroll
            for (int t = 0; t < 2; t++) { c[t][0]=c[t][1]=c[t][2]=c[t][3]=0.f; }
            #pragma unroll
            for (int kc = 0; kc < 2; kc++) {
                const int kb = hh * 32 + kc * 16 + 2 * tig;
                unsigned ahi[4], alo[4];
                ahi[0] = *(const unsigned*)&Qhi[r0 * QSTR + kb];
                ahi[1] = *(const unsigned*)&Qhi[(r0 + 8) * QSTR + kb];
                ahi[2] = *(const unsigned*)&Qhi[r0 * QSTR + kb + 8];
                ahi[3] = *(const unsigned*)&Qhi[(r0 + 8) * QSTR + kb + 8];
                alo[0] = *(const unsigned*)&Qlo[r0 * QSTR + kb];
                alo[1] = *(const unsigned*)&Qlo[(r0 + 8) * QSTR + kb];
                alo[2] = *(const unsigned*)&Qlo[r0 * QSTR + kb + 8];
                alo[3] = *(const unsigned*)&Qlo[(r0 + 8) * QSTR + kb + 8];
                #pragma unroll
                for (int t = 0; t < 2; t++) {
                    if (t < ntn) {
                        const int nr = (nt0 + t) * 8 + g;
                        unsigned bh[2], bl[2];
                        bh[0] = *(const unsigned*)&Khi[nr * QSTR + kb];
                        bh[1] = *(const unsigned*)&Khi[nr * QSTR + kb + 8];
                        bl[0] = *(const unsigned*)&Klo[nr * QSTR + kb];
                        bl[1] = *(const unsigned*)&Klo[nr * QSTR + kb + 8];
                        mma_bf16(c[t], ahi, bh);
                        mma_bf16(c[t], ahi, bl);
                        mma_bf16(c[t], alo, bh);
                    }
                }
            }
            #pragma unroll
            for (int t = 0; t < 2; t++) {
                if (t < ntn) {
                    const int col = (nt0 + t) * 8 + 2 * tig;
                    #pragma unroll
                    for (int half = 0; half < 2; half++) {
                        const int r = r0 + half * 8;
                        if (r < 49) {
                            if (col < 49)
                                LG[r * LGS + col] = c[t][half * 2] + mrow[r * 49 + col];
                            if (col + 1 < 49)
                                LG[r * LGS + col + 1] = c[t][half * 2 + 1]
                                                        + mrow[r * 49 + col + 1];
                        }
                    }
                }
            }
        }
        __syncthreads();
        // ---- softmax (warp per row) ----
        for (int r = wid; r < 49; r += 16) {
            float* row = &LG[r * LGS];
            float v0 = row[lane];
            bool ok1 = (lane + 32) < 49;
            float v1 = ok1 ? row[lane + 32] : -3.0e38f;
            float mx = fmaxf(v0, v1);
            #pragma unroll
            for (int o = 16; o; o >>= 1) mx = fmaxf(mx, __shfl_xor_sync(~0u, mx, o));
            float e0 = __expf(v0 - mx);
            float e1 = ok1 ? __expf(v1 - mx) : 0.f;
            float s = e0 + e1;
            #pragma unroll
            for (int o = 16; o; o >>= 1) s += __shfl_xor_sync(~0u, s, o);
            float inv = 1.0f / s;
            row[lane] = e0 * inv;
            if (ok1) row[lane + 32] = e1 * inv;
        }
        __syncthreads();
        // ---- P @ V_h on tensor cores (3-term split) ----
        {
            const int nt = wid >> 2;               // 0..3 -> 8 dims each
            const int dim_g = hh * 32 + nt * 8 + g;
            float c[4] = {0.f, 0.f, 0.f, 0.f};
            #pragma unroll
            for (int kc = 0; kc < 4; kc++) {
                const int kb = kc * 16 + 2 * tig;
                float2 p00 = *reinterpret_cast<const float2*>(&LG[r0 * LGS + kb]);
                float2 p10 = *reinterpret_cast<const float2*>(&LG[(r0 + 8) * LGS + kb]);
                float2 p01 = *reinterpret_cast<const float2*>(&LG[r0 * LGS + kb + 8]);
                float2 p11 = *reinterpret_cast<const float2*>(&LG[(r0 + 8) * LGS + kb + 8]);
                unsigned ahi[4], alo[4];
                split2(p00.x, p00.y, ahi[0], alo[0]);
                split2(p10.x, p10.y, ahi[1], alo[1]);
                split2(p01.x, p01.y, ahi[2], alo[2]);
                split2(p11.x, p11.y, ahi[3], alo[3]);
                unsigned bh[2], bl[2];
                bh[0] = *(const unsigned*)&Vthi[vt_idx(dim_g, kb)];
                bh[1] = *(const unsigned*)&Vthi[vt_idx(dim_g, kb + 8)];
                bl[0] = *(const unsigned*)&Vtlo[vt_idx(dim_g, kb)];
                bl[1] = *(const unsigned*)&Vtlo[vt_idx(dim_g, kb + 8)];
                mma_bf16(c, ahi, bh);
                mma_bf16(c, ahi, bl);
                mma_bf16(c, alo, bh);
            }
            const int col = hh * 32 + nt * 8 + 2 * tig;
            if (r0 < 49) {
                unsigned hi, lo;
                split2(c[0], c[1], hi, lo);
                *(unsigned*)&Ah[r0 * 200 + col] = hi;
                *(unsigned*)&Al[r0 * 200 + col] = lo;
            }
            if (r0 + 8 < 49) {
                unsigned hi, lo;
                split2(c[2], c[3], hi, lo);
                *(unsigned*)&Ah[(r0 + 8) * 200 + col] = hi;
                *(unsigned*)&Al[(r0 + 8) * 200 + col] = lo;
            }
        }
    }
    __syncthreads();   // P@V LG reads done before proj stages over LG region

    gemm_mma<0>(g_Phi, g_Plo, proj_b, 1.0f, out + (size_t)b * 9408, nullptr, nullptr);
}

extern "C" void kernel_launch(void* const* d_in, const int* in_sizes, int n_in,
                              void* d_out, int out_size) {
    const float* x      = (const float*)d_in[0];
    const float* mask   = (const float*)d_in[1];
    const float* qkv_w  = (const float*)d_in[2];
    const float* qkv_b  = (const float*)d_in[3];
    const float* proj_w = (const float*)d_in[4];
    const float* proj_b = (const float*)d_in[5];
    const float* rope   = (const float*)d_in[6];
    float* out = (float*)d_out;

    prep_weights<<<432, 256>>>(qkv_w, proj_w);
    cudaFuncSetAttribute(swin_fused_kernel,
                         cudaFuncAttributeMaxDynamicSharedMemorySize, SMEM_BYTES);
    swin_fused_kernel<<<4096, THREADS, SMEM_BYTES>>>(
        x, mask, qkv_b, proj_b, rope, out);
}

// round 9
// speedup vs baseline: 1.8693x; 1.1864x over previous
#include <cuda_runtime.h>
#include <cuda_bf16.h>
#include <float.h>

#define THREADS 384
// ---- smem byte offsets ----
#define AHI_OFF 0          // x / attn-out hi [64][200] bf16
#define ALO_OFF 25600
#define WST_OFF 51200      // W stage [2buf][2hl][192][48B] = 36864 ; mask aliases here
#define QHI_OFF 88064      // [64][196] bf16
#define QLO_OFF 113152
#define KHI_OFF 138240     // [56][196] bf16
#define KLO_OFF 160192
#define VTH_OFF 182144     // V^T [192][64] bf16, XOR-swizzled tokens
#define VTL_OFF 206720
#define RT_OFF  231296     // rope freqs copy, 192 floats
#define SMEM_BYTES 232064
#define QSTR 196

__device__ __nv_bfloat16 g_Whi[110592];
__device__ __nv_bfloat16 g_Wlo[110592];
__device__ __nv_bfloat16 g_Phi[36864];
__device__ __nv_bfloat16 g_Plo[36864];

__global__ void prep_weights(const float* __restrict__ qkv_w,
                             const float* __restrict__ proj_w) {
    int i = blockIdx.x * 256 + threadIdx.x;
    if (i < 110592) {
        float v = qkv_w[i];
        __nv_bfloat16 h = __float2bfloat16(v);
        g_Whi[i] = h;
        g_Wlo[i] = __float2bfloat16(v - __bfloat162float(h));
    }
    if (i < 36864) {
        float v = proj_w[i];
        __nv_bfloat16 h = __float2bfloat16(v);
        g_Phi[i] = h;
        g_Plo[i] = __float2bfloat16(v - __bfloat162float(h));
    }
}

__device__ __forceinline__ unsigned pkbf(__nv_bfloat16 a, __nv_bfloat16 b) {
    return (unsigned)__bfloat16_as_ushort(a) | ((unsigned)__bfloat16_as_ushort(b) << 16);
}
__device__ __forceinline__ void split2(float x, float y, unsigned& hi, unsigned& lo) {
    __nv_bfloat16 h0 = __float2bfloat16(x), h1 = __float2bfloat16(y);
    __nv_bfloat16 l0 = __float2bfloat16(x - __bfloat162float(h0));
    __nv_bfloat16 l1 = __float2bfloat16(y - __bfloat162float(h1));
    hi = pkbf(h0, h1);
    lo = pkbf(l0, l1);
}
__device__ __forceinline__ void mma_bf16(float* c, const unsigned* a, const unsigned* b) {
    asm volatile(
        "mma.sync.aligned.m16n8k16.row.col.f32.bf16.bf16.f32 "
        "{%0,%1,%2,%3}, {%4,%5,%6,%7}, {%8,%9}, {%0,%1,%2,%3};\n"
        : "+f"(c[0]), "+f"(c[1]), "+f"(c[2]), "+f"(c[3])
        : "r"(a[0]), "r"(a[1]), "r"(a[2]), "r"(a[3]), "r"(b[0]), "r"(b[1]));
}
__device__ __forceinline__ void ldsm4(unsigned* r, unsigned addr) {
    asm volatile("ldmatrix.sync.aligned.m8n8.x4.shared.b16 {%0,%1,%2,%3}, [%4];\n"
                 : "=r"(r[0]), "=r"(r[1]), "=r"(r[2]), "=r"(r[3]) : "r"(addr));
}
__device__ __forceinline__ int vt_idx(int dim, int tok) {
    return dim * 64 + (tok ^ ((dim & 7) << 3));
}

// C[49][192] = A(hi+lo)[64][192] @ W^T + bias (scaled).  12-warp version.
// MODE 0: fp32 -> outp. MODE 1: RoPE -> bf16 hi/lo. MODE 2: transposed swizzled -> V^T.
template <int MODE>
__device__ __noinline__ void gemm_mma(const __nv_bfloat16* __restrict__ Whi,
                                      const __nv_bfloat16* __restrict__ Wlo,
                                      const float* __restrict__ bias, float scale,
                                      float* __restrict__ outp,
                                      __nv_bfloat16* __restrict__ ohi,
                                      __nv_bfloat16* __restrict__ olo) {
    extern __shared__ char smem[];
    const __nv_bfloat16* Ah = (const __nv_bfloat16*)(smem + AHI_OFF);
    const __nv_bfloat16* Al = (const __nv_bfloat16*)(smem + ALO_OFF);
    const float* RT = (const float*)(smem + RT_OFF);
    char* wst = smem + WST_OFF;
    const unsigned wst_u32 = (unsigned)__cvta_generic_to_shared(wst);

    const int tid = threadIdx.x;
    const int wid = tid >> 5, lane = tid & 31;
    const int g = lane >> 2, tig = lane & 3;
    const int mt = wid & 3;          // 16-row tile
    const int nq = wid >> 2;         // 64-col third (0..2)
    const int grp = lane >> 3;
    const unsigned lm_off = (unsigned)(((grp >> 1) * 8 + (lane & 7)) * 48 + (grp & 1) * 16);

    const int n0 = tid % 192, q0 = tid / 192;         // q0: 0..1 (hi)
    const int hf0 = q0 & 1;
    const int i1 = tid + 384;
    const int n1 = i1 % 192, q1 = i1 / 192;           // q1: 2..3 (lo)
    const int hf1 = q1 & 1;

    float acc[8][4];
    #pragma unroll
    for (int t = 0; t < 8; t++) { acc[t][0]=acc[t][1]=acc[t][2]=acc[t][3]=0.f; }

    {   // stage k-panel 0
        float4 v = *reinterpret_cast<const float4*>(Whi + n0 * 192 + hf0 * 8);
        *reinterpret_cast<float4*>(wst + n0 * 48 + hf0 * 16) = v;
        float4 w = *reinterpret_cast<const float4*>(Wlo + n1 * 192 + hf1 * 8);
        *reinterpret_cast<float4*>(wst + 9216 + n1 * 48 + hf1 * 16) = w;
    }
    __syncthreads();

    for (int k = 0; k < 12; k++) {
        const int buf = k & 1;
        float4 pf0, pf1;
        if (k < 11) {
            pf0 = *reinterpret_cast<const float4*>(Whi + n0 * 192 + (k + 1) * 16 + hf0 * 8);
            pf1 = *reinterpret_cast<const float4*>(Wlo + n1 * 192 + (k + 1) * 16 + hf1 * 8);
        }
        unsigned ahi[4], alo[4];
        {
            const int r0 = mt * 16 + g;
            const int kb = k * 16 + 2 * tig;
            ahi[0] = *(const unsigned*)&Ah[r0 * 200 + kb];
            ahi[1] = *(const unsigned*)&Ah[(r0 + 8) * 200 + kb];
            ahi[2] = *(const unsigned*)&Ah[r0 * 200 + kb + 8];
            ahi[3] = *(const unsigned*)&Ah[(r0 + 8) * 200 + kb + 8];
            alo[0] = *(const unsigned*)&Al[r0 * 200 + kb];
            alo[1] = *(const unsigned*)&Al[(r0 + 8) * 200 + kb];
            alo[2] = *(const unsigned*)&Al[r0 * 200 + kb + 8];
            alo[3] = *(const unsigned*)&Al[(r0 + 8) * 200 + kb + 8];
        }
        const unsigned base_h = wst_u32 + (unsigned)(buf * 18432) + lm_off;
        #pragma unroll
        for (int p = 0; p < 4; p++) {
            unsigned bh[4], bl[4];
            unsigned ad = base_h + (unsigned)((nq * 64 + 16 * p) * 48);
            ldsm4(bh, ad);
            ldsm4(bl, ad + 9216);
            mma_bf16(acc[2 * p], ahi, bh);
            mma_bf16(acc[2 * p], ahi, bl);
            mma_bf16(acc[2 * p], alo, bh);
            mma_bf16(acc[2 * p + 1], ahi, bh + 2);
            mma_bf16(acc[2 * p + 1], ahi, bl + 2);
            mma_bf16(acc[2 * p + 1], alo, bh + 2);
        }
        if (k < 11) {
            *reinterpret_cast<float4*>(wst + (buf ^ 1) * 18432 + n0 * 48 + hf0 * 16) = pf0;
            *reinterpret_cast<float4*>(wst + (buf ^ 1) * 18432 + 9216 + n1 * 48 + hf1 * 16) = pf1;
            __syncthreads();
        }
    }

    const int r0 = mt * 16 + g;
    #pragma unroll
    for (int t = 0; t < 8; t++) {
        const int col = nq * 64 + t * 8 + 2 * tig;
        float2 bb = *reinterpret_cast<const float2*>(&bias[col]);
        float fx, fy;
        if (MODE == 1) {
            int hh = col >> 5, d = (col & 31) >> 1;
            fx = RT[hh * 16 + d];
            fy = RT[96 + hh * 16 + d];
        }
        #pragma unroll
        for (int half = 0; half < 2; half++) {
            const int r = r0 + half * 8;
            if (r < 49) {
                float vx = (acc[t][half * 2 + 0] + bb.x) * scale;
                float vy = (acc[t][half * 2 + 1] + bb.y) * scale;
                if (MODE == 0) {
                    *reinterpret_cast<float2*>(&outp[r * 192 + col]) = make_float2(vx, vy);
                } else if (MODE == 1) {
                    float ang = (float)(r % 7) * fx + (float)(r / 7) * fy;
                    float sv, cv;
                    sincosf(ang, &sv, &cv);
                    float re = vx * cv - vy * sv;
                    float im = vx * sv + vy * cv;
                    unsigned hi, lo;
                    split2(re, im, hi, lo);
                    *(unsigned*)&ohi[r * QSTR + col] = hi;
                    *(unsigned*)&olo[r * QSTR + col] = lo;
                } else {
                    __nv_bfloat16 h0 = __float2bfloat16(vx);
                    __nv_bfloat16 l0 = __float2bfloat16(vx - __bfloat162float(h0));
                    __nv_bfloat16 h1 = __float2bfloat16(vy);
                    __nv_bfloat16 l1 = __float2bfloat16(vy - __bfloat162float(h1));
                    ohi[vt_idx(col, r)] = h0;
                    olo[vt_idx(col, r)] = l0;
                    ohi[vt_idx(col + 1, r)] = h1;
                    olo[vt_idx(col + 1, r)] = l1;
                }
            }
        }
    }
}

__global__ void __launch_bounds__(THREADS, 1)
swin_fused_kernel(const float* __restrict__ x,
                  const float* __restrict__ mask,
                  const float* __restrict__ qkv_b,
                  const float* __restrict__ proj_b,
                  const float* __restrict__ rope,
                  float* __restrict__ out)
{
    extern __shared__ char smem[];
    __nv_bfloat16* Ah   = (__nv_bfloat16*)(smem + AHI_OFF);
    __nv_bfloat16* Al   = (__nv_bfloat16*)(smem + ALO_OFF);
    __nv_bfloat16* Qhi  = (__nv_bfloat16*)(smem + QHI_OFF);
    __nv_bfloat16* Qlo  = (__nv_bfloat16*)(smem + QLO_OFF);
    __nv_bfloat16* Khi  = (__nv_bfloat16*)(smem + KHI_OFF);
    __nv_bfloat16* Klo  = (__nv_bfloat16*)(smem + KLO_OFF);
    __nv_bfloat16* Vthi = (__nv_bfloat16*)(smem + VTH_OFF);
    __nv_bfloat16* Vtlo = (__nv_bfloat16*)(smem + VTL_OFF);
    float* MSK = (float*)(smem + WST_OFF);   // mask staged over idle W-stage
    float* RT  = (float*)(smem + RT_OFF);
    const int tid = threadIdx.x;
    const int b = blockIdx.x;
    const int lane = tid & 31, wid = tid >> 5;
    const int g = lane >> 2, tig = lane & 3;

    // ---- prologue ----
    for (int i = tid; i < 4704; i += THREADS) {
        int n = i / 96, c = i % 96;
        float2 v = *reinterpret_cast<const float2*>(&x[(size_t)b * 9408 + n * 192 + 2 * c]);
        unsigned hi, lo;
        split2(v.x, v.y, hi, lo);
        *(unsigned*)&Ah[n * 200 + 2 * c] = hi;
        *(unsigned*)&Al[n * 200 + 2 * c] = lo;
    }
    for (int i = tid; i < 15 * 96; i += THREADS) {     // A pad rows 49..63
        int r = 49 + i / 96, c = i % 96;
        *(unsigned*)&Ah[r * 200 + 2 * c] = 0u;
        *(unsigned*)&Al[r * 200 + 2 * c] = 0u;
    }
    for (int i = tid; i < 15 * 98; i += THREADS) {     // Q pad rows 49..63
        int r = 49 + i / 98, c = i % 98;
        *(unsigned*)&Qhi[r * QSTR + 2 * c] = 0u;
        *(unsigned*)&Qlo[r * QSTR + 2 * c] = 0u;
    }
    for (int i = tid; i < 7 * 98; i += THREADS) {      // K pad rows 49..55
        int r = 49 + i / 98, c = i % 98;
        *(unsigned*)&Khi[r * QSTR + 2 * c] = 0u;
        *(unsigned*)&Klo[r * QSTR + 2 * c] = 0u;
    }
    {   // zero V^T hi+lo
        float4* vz = reinterpret_cast<float4*>(smem + VTH_OFF);
        for (int i = tid; i < 3072; i += THREADS) vz[i] = make_float4(0.f, 0.f, 0.f, 0.f);
    }
    if (tid < 192) RT[tid] = rope[tid];
    // gemm's first internal __syncthreads orders the fills

    gemm_mma<1>(g_Whi,         g_Wlo,         qkv_b,       0.17677669529663687f,
                nullptr, Qhi, Qlo);
    gemm_mma<1>(g_Whi + 36864, g_Wlo + 36864, qkv_b + 192, 1.0f, nullptr, Khi, Klo);
    gemm_mma<2>(g_Whi + 73728, g_Wlo + 73728, qkv_b + 384, 1.0f, nullptr, Vthi, Vtlo);
    __syncthreads();   // gemm<2> WST reads done; V^T written

    // stage shift mask into idle WST region
    {
        const float* mrow = mask + (size_t)(b & 63) * 2401;
        for (int i = tid; i < 2401; i += THREADS) MSK[i] = mrow[i];
    }
    __syncthreads();   // mask + V^T visible to all

    // ---- barrier-free attention: warp-owned (head, m-tile) slots ----
    #pragma unroll 1
    for (int si = 0; si < 2; si++) {
        const int slot = wid + 12 * si;     // 0..23
        const int hh = slot >> 2, mt2 = slot & 3;
        const int r0 = mt2 * 16 + g;
        const int r1 = r0 + 8;
        float c[8][4];
        #pragma unroll
        for (int t = 0; t < 8; t++) { c[t][0]=c[t][1]=c[t][2]=c[t][3]=0.f; }

        // logits = q_h @ k_h^T   (3-term split-bf16; C-frag layout == A-frag for P@V)
        #pragma unroll
        for (int kc = 0; kc < 2; kc++) {
            const int kb = hh * 32 + kc * 16 + 2 * tig;
            unsigned ahi[4], alo[4];
            ahi[0] = *(const unsigned*)&Qhi[r0 * QSTR + kb];
            ahi[1] = *(const unsigned*)&Qhi[r1 * QSTR + kb];
            ahi[2] = *(const unsigned*)&Qhi[r0 * QSTR + kb + 8];
            ahi[3] = *(const unsigned*)&Qhi[r1 * QSTR + kb + 8];
            alo[0] = *(const unsigned*)&Qlo[r0 * QSTR + kb];
            alo[1] = *(const unsigned*)&Qlo[r1 * QSTR + kb];
            alo[2] = *(const unsigned*)&Qlo[r0 * QSTR + kb + 8];
            alo[3] = *(const unsigned*)&Qlo[r1 * QSTR + kb + 8];
            #pragma unroll
            for (int t = 0; t < 7; t++) {
                const int nr = t * 8 + g;
                unsigned bh[2], bl[2];
                bh[0] = *(const unsigned*)&Khi[nr * QSTR + kb];
                bh[1] = *(const unsigned*)&Khi[nr * QSTR + kb + 8];
                bl[0] = *(const unsigned*)&Klo[nr * QSTR + kb];
                bl[1] = *(const unsigned*)&Klo[nr * QSTR + kb + 8];
                mma_bf16(c[t], ahi, bh);
                mma_bf16(c[t], ahi, bl);
                mma_bf16(c[t], alo, bh);
            }
        }
        // mask add + column bounds
        #pragma unroll
        for (int t = 0; t < 8; t++) {
            const int col = t * 8 + 2 * tig;
            if (col < 49) {
                if (r0 < 49) c[t][0] += MSK[r0 * 49 + col];
                if (r1 < 49) c[t][2] += MSK[r1 * 49 + col];
            } else { c[t][0] = -FLT_MAX; c[t][2] = -FLT_MAX; }
            if (col + 1 < 49) {
                if (r0 < 49) c[t][1] += MSK[r0 * 49 + col + 1];
                if (r1 < 49) c[t][3] += MSK[r1 * 49 + col + 1];
            } else { c[t][1] = -FLT_MAX; c[t][3] = -FLT_MAX; }
        }
        // softmax per row (row data lives in a quad; 2 shuffles per reduction)
        {
            float mx0 = -FLT_MAX, mx1 = -FLT_MAX;
            #pragma unroll
            for (int t = 0; t < 8; t++) {
                mx0 = fmaxf(mx0, fmaxf(c[t][0], c[t][1]));
                mx1 = fmaxf(mx1, fmaxf(c[t][2], c[t][3]));
            }
            #pragma unroll
            for (int o = 1; o <= 2; o <<= 1) {
                mx0 = fmaxf(mx0, __shfl_xor_sync(~0u, mx0, o));
                mx1 = fmaxf(mx1, __shfl_xor_sync(~0u, mx1, o));
            }
            float s0 = 0.f, s1 = 0.f;
            #pragma unroll
            for (int t = 0; t < 8; t++) {
                c[t][0] = __expf(c[t][0] - mx0); s0 += c[t][0];
                c[t][1] = __expf(c[t][1] - mx0); s0 += c[t][1];
                c[t][2] = __expf(c[t][2] - mx1); s1 += c[t][2];
                c[t][3] = __expf(c[t][3] - mx1); s1 += c[t][3];
            }
            #pragma unroll
            for (int o = 1; o <= 2; o <<= 1) {
                s0 += __shfl_xor_sync(~0u, s0, o);
                s1 += __shfl_xor_sync(~0u, s1, o);
            }
            float i0 = 1.0f / s0, i1 = 1.0f / s1;
            #pragma unroll
            for (int t = 0; t < 8; t++) {
                c[t][0] *= i0; c[t][1] *= i0; c[t][2] *= i1; c[t][3] *= i1;
            }
        }
        // P @ V_h : P fragments are reinterpreted logits registers
        float o[4][4];
        #pragma unroll
        for (int dt = 0; dt < 4; dt++) { o[dt][0]=o[dt][1]=o[dt][2]=o[dt][3]=0.f; }
        #pragma unroll
        for (int kc = 0; kc < 4; kc++) {
            unsigned phi[4], plo[4];
            split2(c[2 * kc][0], c[2 * kc][1], phi[0], plo[0]);
            split2(c[2 * kc][2], c[2 * kc][3], phi[1], plo[1]);
            split2(c[2 * kc + 1][0], c[2 * kc + 1][1], phi[2], plo[2]);
            split2(c[2 * kc + 1][2], c[2 * kc + 1][3], phi[3], plo[3]);
            const int kb = kc * 16 + 2 * tig;
            #pragma unroll
            for (int dt = 0; dt < 4; dt++) {
                const int dim_g = hh * 32 + dt * 8 + g;
                unsigned bh[2], bl[2];
                bh[0] = *(const unsigned*)&Vthi[vt_idx(dim_g, kb)];
                bh[1] = *(const unsigned*)&Vthi[vt_idx(dim_g, kb + 8)];
                bl[0] = *(const unsigned*)&Vtlo[vt_idx(dim_g, kb)];
                bl[1] = *(const unsigned*)&Vtlo[vt_idx(dim_g, kb + 8)];
                mma_bf16(o[dt], phi, bh);
                mma_bf16(o[dt], phi, bl);
                mma_bf16(o[dt], plo, bh);
            }
        }
        #pragma unroll
        for (int dt = 0; dt < 4; dt++) {
            const int col = hh * 32 + dt * 8 + 2 * tig;
            if (r0 < 49) {
                unsigned hi, lo;
                split2(o[dt][0], o[dt][1], hi, lo);
                *(unsigned*)&Ah[r0 * 200 + col] = hi;
                *(unsigned*)&Al[r0 * 200 + col] = lo;
            }
            if (r1 < 49) {
                unsigned hi, lo;
                split2(o[dt][2], o[dt][3], hi, lo);
                *(unsigned*)&Ah[r1 * 200 + col] = hi;
                *(unsigned*)&Al[r1 * 200 + col] = lo;
            }
        }
    }
    __syncthreads();   // attention writes to Ah/Al done; WST free again

    gemm_mma<0>(g_Phi, g_Plo, proj_b, 1.0f, out + (size_t)b * 9408, nullptr, nullptr);
}

extern "C" void kernel_launch(void* const* d_in, const int* in_sizes, int n_in,
                              void* d_out, int out_size) {
    const float* x      = (const float*)d_in[0];
    const float* mask   = (const float*)d_in[1];
    const float* qkv_w  = (const float*)d_in[2];
    const float* qkv_b  = (const float*)d_in[3];
    const float* proj_w = (const float*)d_in[4];
    const float* proj_b = (const float*)d_in[5];
    const float* rope   = (const float*)d_in[6];
    float* out = (float*)d_out;

    prep_weights<<<432, 256>>>(qkv_w, proj_w);
    cudaFuncSetAttribute(swin_fused_kernel,
                         cudaFuncAttributeMaxDynamicSharedMemorySize, SMEM_BYTES);
    swin_fused_kernel<<<4096, THREADS, SMEM_BYTES>>>(
        x, mask, qkv_b, proj_b, rope, out);
}